// round 15
// baseline (speedup 1.0000x reference)
#include <cuda_runtime.h>
#include <cuda_fp16.h>
#include <cstdint>

// Problem constants
static constexpr int BB = 1024;   // batch
static constexpr int NI = 2048;
static constexpr int NH = 4096;
static constexpr int NO = 1024;
static constexpr int CC = 4;      // LSTM cell size
static constexpr int KTOT = NI + NH;     // 6144
static constexpr int KHALF = KTOT / 2;   // 3072

// ---------------------------------------------------------------------------
// Device scratch (no cudaMalloc allowed)
// ---------------------------------------------------------------------------
__device__ float g_inh[2 * (size_t)BB * NH];   // split-K partials
__device__ float g_ino[2 * (size_t)BB * NO];

__device__ __align__(16) __half g_i_f16[(size_t)BB * NI];
__device__ __align__(16) __half g_h_f16[(size_t)BB * NH];
__device__ __align__(16) __half g_w1h_f16[(size_t)NH * NI];
__device__ __align__(16) __half g_w2h_f16[(size_t)NH * NH];
__device__ __align__(16) __half g_w1o_f16[(size_t)NO * NI];
__device__ __align__(16) __half g_w2o_f16[(size_t)NO * NH];

// ---------------------------------------------------------------------------
// PTX helpers (portable ISA only: cp.async, ldmatrix, mma.sync)
// ---------------------------------------------------------------------------
__device__ __forceinline__ uint32_t smem_u32(const void* p) {
    uint32_t a;
    asm("{ .reg .u64 t; cvta.to.shared.u64 t, %1; cvt.u32.u64 %0, t; }"
        : "=r"(a) : "l"(p));
    return a;
}

__device__ __forceinline__ void cp16(uint32_t dst, const void* src) {
    asm volatile("cp.async.cg.shared.global [%0], [%1], 16;\n"
                 :: "r"(dst), "l"(src));
}
__device__ __forceinline__ void cp_commit() {
    asm volatile("cp.async.commit_group;\n" ::: "memory");
}
template <int N> __device__ __forceinline__ void cp_wait() {
    asm volatile("cp.async.wait_group %0;\n" :: "n"(N) : "memory");
}

__device__ __forceinline__ void ldmx4(uint32_t* r, uint32_t addr) {
    asm volatile("ldmatrix.sync.aligned.m8n8.x4.shared.b16 {%0,%1,%2,%3}, [%4];"
                 : "=r"(r[0]), "=r"(r[1]), "=r"(r[2]), "=r"(r[3]) : "r"(addr));
}

__device__ __forceinline__ void mma16816(float* c, const uint32_t* a, const uint32_t* b) {
    asm volatile(
        "mma.sync.aligned.m16n8k16.row.col.f32.f16.f16.f32 "
        "{%0,%1,%2,%3}, {%4,%5,%6,%7}, {%8,%9}, {%0,%1,%2,%3};"
        : "+f"(c[0]), "+f"(c[1]), "+f"(c[2]), "+f"(c[3])
        : "r"(a[0]), "r"(a[1]), "r"(a[2]), "r"(a[3]), "r"(b[0]), "r"(b[1]));
}

__device__ __forceinline__ uint32_t pack2h(float lo, float hi) {
    __half2 h = __floats2half2_rn(lo, hi);
    return *(uint32_t*)&h;
}

// Fast transcendentals (hardware MUFU-based, err ~1e-6 — far under budget)
__device__ __forceinline__ float fsig(float x) {
    return __fdividef(1.f, 1.f + __expf(-x));
}
__device__ __forceinline__ float ftanh(float x) {
    return fmaf(2.f, fsig(2.f * x), -1.f);
}

// ---------------------------------------------------------------------------
// Fused fp32 -> fp16 convert over all 6 tensors (1 launch, 4 float4/thread)
// ---------------------------------------------------------------------------
static constexpr size_t S0 = (size_t)BB * NI / 4;            // i
static constexpr size_t S1 = S0 + (size_t)BB * NH / 4;       // h
static constexpr size_t S2 = S1 + (size_t)NH * NI / 4;       // W_i2h
static constexpr size_t S3 = S2 + (size_t)NH * NH / 4;       // W_h2h
static constexpr size_t S4 = S3 + (size_t)NO * NI / 4;       // W_i2o
static constexpr size_t S5 = S4 + (size_t)NO * NH / 4;       // W_h2o

__global__ __launch_bounds__(256) void cvt_all(
    const float4* __restrict__ p0, const float4* __restrict__ p1,
    const float4* __restrict__ p2, const float4* __restrict__ p3,
    const float4* __restrict__ p4, const float4* __restrict__ p5,
    uint2* __restrict__ h0, uint2* __restrict__ h1,
    uint2* __restrict__ h2, uint2* __restrict__ h3,
    uint2* __restrict__ h4, uint2* __restrict__ h5)
{
#pragma unroll
    for (int rep = 0; rep < 4; ++rep) {
        size_t i = (size_t)blockIdx.x * 1024 + rep * 256 + threadIdx.x;
        const float4* src; uint2* hi; size_t base;
        if      (i < S0) { src = p0; hi = h0; base = 0;  }
        else if (i < S1) { src = p1; hi = h1; base = S0; }
        else if (i < S2) { src = p2; hi = h2; base = S1; }
        else if (i < S3) { src = p3; hi = h3; base = S2; }
        else if (i < S4) { src = p4; hi = h4; base = S3; }
        else             { src = p5; hi = h5; base = S4; }
        size_t j = i - base;
        float4 v = src[j];
        uint2 H;
        H.x = pack2h(v.x, v.y);
        H.y = pack2h(v.z, v.w);
        hi[j] = H;
    }
}

// ---------------------------------------------------------------------------
// Combined split-K2 mma.sync GEMM (pure fp16), CTA tile 128x64, one launch.
//   blockIdx.x in [0, 1280): kh = bid & 1 (K half), tb = bid >> 1 (tile id)
//     tb [0,512):   inh tile: m0=(tb>>6)*128, n0=(tb&63)*64   (N=4096)
//     tb [512,640): ino tile: m0=(r>>4)*128,  n0=(r&15)*64    (N=1024)
// NO bias/ReLU here: partials reduced (+bias+ReLU) in lstm_pointwise.
// 512 threads = 16 warps (8m x 2n), warp tile 16x32, BK=64.
// 4-stage cp.async pipeline with ONE barrier per chunk: the write at iter c
// targets stage (c+3)%4 whose last readers (chunk c-1) are already past this
// iteration's barrier by program order — no second barrier needed.
// ---------------------------------------------------------------------------
__global__ __launch_bounds__(512, 1) void gemm_f16(
    const __half* __restrict__ iF, const __half* __restrict__ hF,
    const __half* __restrict__ w1h, const __half* __restrict__ w2h,
    const __half* __restrict__ w1o, const __half* __restrict__ w2o,
    float* __restrict__ outh, float* __restrict__ outo)
{
    constexpr int ROWB  = 144;             // 64 fp16 = 128B + 16B pad
    constexpr int ATILE = 128 * ROWB;      // 18432 B
    constexpr int WTILE = 64 * ROWB;       //  9216 B
    constexpr int STAGE = ATILE + WTILE;   // 27648 B

    extern __shared__ char smraw[];
    const uint32_t sb = smem_u32(smraw);

    const int t = threadIdx.x, wid = t >> 5, lane = t & 31;
    const int wm = wid >> 1, wn = wid & 1;   // 8m x 2n, warp tile 16x32

    const int bid = blockIdx.x;
    const int kh = bid & 1;
    const int tb = bid >> 1;
    const int kbase = kh * KHALF;

    const __half *W1, *W2;
    float* out;
    int m0, n0, N;
    if (tb < 512) {
        m0 = (tb >> 6) * 128; n0 = (tb & 63) * 64; N = NH;
        W1 = w1h; W2 = w2h;
        out = outh + (size_t)kh * BB * NH;
    } else {
        int r = tb - 512;
        m0 = (r >> 4) * 128; n0 = (r & 15) * 64; N = NO;
        W1 = w1o; W2 = w2o;
        out = outo + (size_t)kh * BB * NO;
    }

    // ldmatrix per-lane byte offsets within a tile
    const uint32_t aOff = (uint32_t)((wm * 16 + (lane & 15)) * ROWB + (lane >> 4) * 16);
    const uint32_t bOff = (uint32_t)((wn * 32 + ((lane >> 4) << 3) + (lane & 7)) * ROWB
                                     + ((lane >> 3) & 1) * 16);

    float acc[4][4];
#pragma unroll
    for (int j = 0; j < 4; ++j)
#pragma unroll
        for (int k = 0; k < 4; ++k) acc[j][k] = 0.f;

    constexpr int NC = KHALF / 64;   // 48 chunks

    auto load_chunk = [&](int c, int s) {
        const int k0 = kbase + c * 64;
        const __half *Ap, *Wp;
        int lda, ko;
        if (k0 < NI) { Ap = iF; Wp = W1; lda = NI; ko = k0; }
        else         { Ap = hF; Wp = W2; lda = NH; ko = k0 - NI; }
        const uint32_t st = sb + (uint32_t)s * STAGE;
        // A: 128 rows x 8 x 16B = 1024 transfers (2 per thread)
#pragma unroll
        for (int q = 0; q < 2; ++q) {
            int idx = q * 512 + t;
            int row = idx >> 3, ch = idx & 7;
            cp16(st + (uint32_t)(row * ROWB + ch * 16),
                 Ap + (size_t)(m0 + row) * lda + ko + ch * 8);
        }
        // W: 64 rows x 8 x 16B = 512 transfers (1 per thread)
        {
            int row = t >> 3, ch = t & 7;
            cp16(st + ATILE + (uint32_t)(row * ROWB + ch * 16),
                 Wp + (size_t)(n0 + row) * lda + ko + ch * 8);
        }
    };

    // Prologue: fill 3 of the 4 stages
    load_chunk(0, 0); cp_commit();
    load_chunk(1, 1); cp_commit();
    load_chunk(2, 2); cp_commit();

    for (int c = 0; c < NC; ++c) {
        cp_wait<2>();                // chunk c's groups retired
        __syncthreads();             // all warps see stage c%4; also proves all
                                     // warps finished reading stage (c+3)%4
        if (c + 3 < NC) load_chunk(c + 3, (c + 3) & 3);
        cp_commit();                 // one group per iteration (empty at tail)

        const uint32_t ast = sb + (uint32_t)(c & 3) * STAGE;
        const uint32_t wst = ast + ATILE;
#pragma unroll
        for (int kk = 0; kk < 4; ++kk) {
            uint32_t ah[4];
            ldmx4(ah, ast + aOff + (uint32_t)(kk * 32));
            uint32_t bh[2][4];
#pragma unroll
            for (int p = 0; p < 2; ++p)
                ldmx4(bh[p], wst + bOff + (uint32_t)(p * 16 * ROWB + kk * 32));
#pragma unroll
            for (int nt = 0; nt < 4; ++nt)
                mma16816(acc[nt], ah, &bh[nt >> 1][(nt & 1) * 2]);
        }
    }

    // Epilogue: raw partial store (bias/ReLU applied at reduce in pointwise)
    const int g = lane >> 2, q2 = (lane & 3) * 2;
#pragma unroll
    for (int nt = 0; nt < 4; ++nt) {
        int col = n0 + wn * 32 + nt * 8 + q2;
        int r0 = m0 + wm * 16 + g;
        *(float2*)&out[(size_t)r0 * N + col] = make_float2(acc[nt][0], acc[nt][1]);
        *(float2*)&out[(size_t)(r0 + 8) * N + col] = make_float2(acc[nt][2], acc[nt][3]);
    }
}

// ---------------------------------------------------------------------------
// Fused per-node LSTM pointwise for BOTH nets in one launch, with
// split-K reduce + agg bias + ReLU:  x = relu(xp0 + xp1 + ab1[n] + ab2[n])
//   blockIdx.x [0,128): h-net (N=4096), [128,160): o-net (N=1024)
// ---------------------------------------------------------------------------
__global__ __launch_bounds__(256) void lstm_pointwise2(
    const float* __restrict__ xph, const float* __restrict__ b_i2h,
    const float* __restrict__ b_h2h,
    const float* __restrict__ h_in, const float* __restrict__ h_cells,
    const float* __restrict__ Wih_h, const float* __restrict__ Whh_h,
    const float* __restrict__ bias_h, const float* __restrict__ Whr_h,
    float* __restrict__ new_h, float* __restrict__ new_hc,
    const float* __restrict__ xpo, const float* __restrict__ b_i2o,
    const float* __restrict__ b_h2o,
    const float* __restrict__ o_in, const float* __restrict__ o_cells,
    const float* __restrict__ Wih_o, const float* __restrict__ Whh_o,
    const float* __restrict__ bias_o, const float* __restrict__ Whr_o,
    float* __restrict__ new_o, float* __restrict__ new_oc)
{
    __shared__ float sX[32][33];
    __shared__ float sH[32][33];
    __shared__ float sHn[32][33];
    __shared__ float sWih[32][16];
    __shared__ float sWhh[32][16];
    __shared__ float sBias[32][16];
    __shared__ float sWhr[32][4];
    __shared__ float sAggB[32];

    const int t = threadIdx.x;
    const int bx = blockIdx.x;
    const int b0 = blockIdx.y * 32;

    const float *xp0, *ab1, *ab2, *hprev, *cprev, *Wih, *Whh, *bias, *Whr;
    float *hnew, *cnew;
    int N, n0;
    if (bx < NH / 32) {
        N = NH; n0 = bx * 32;
        xp0 = xph; ab1 = b_i2h; ab2 = b_h2h; hprev = h_in; cprev = h_cells;
        Wih = Wih_h; Whh = Whh_h; bias = bias_h; Whr = Whr_h;
        hnew = new_h; cnew = new_hc;
    } else {
        N = NO; n0 = (bx - NH / 32) * 32;
        xp0 = xpo; ab1 = b_i2o; ab2 = b_h2o; hprev = o_in; cprev = o_cells;
        Wih = Wih_o; Whh = Whh_o; bias = bias_o; Whr = Whr_o;
        hnew = new_o; cnew = new_oc;
    }
    const float* xp1 = xp0 + (size_t)BB * N;   // second split-K partial
    const int B = BB;

    if (t < 128) {
        int nl = t >> 2, w = t & 3;
        ((float4*)&sWih[nl][0])[w]  = ((const float4*)Wih)[(size_t)(n0 + nl) * 4 + w];
        ((float4*)&sWhh[nl][0])[w]  = ((const float4*)Whh)[(size_t)(n0 + nl) * 4 + w];
        ((float4*)&sBias[nl][0])[w] = ((const float4*)bias)[(size_t)(n0 + nl) * 4 + w];
    }
    if (t < 32) {
        *(float4*)&sWhr[t][0] = ((const float4*)Whr)[(size_t)(n0 + t)];
        sAggB[t] = ab1[n0 + t] + ab2[n0 + t];
    }

#pragma unroll
    for (int q = 0; q < 4; ++q) {
        int idx = t + 256 * q;
        int bl = idx >> 5, nl = idx & 31;
        size_t gi = (size_t)(b0 + bl) * N + n0 + nl;
        sX[bl][nl] = xp0[gi] + xp1[gi];
        sH[bl][nl] = hprev[gi];
    }
    __syncthreads();

#pragma unroll
    for (int q = 0; q < 4; ++q) {
        int idx = t + 256 * q;
        int bl = idx & 31, nl = idx >> 5;
        int n = n0 + nl, b = b0 + bl;

        float x  = fmaxf(sX[bl][nl] + sAggB[nl], 0.f);   // reduce + bias + ReLU
        float hp = sH[bl][nl];

        float g[16];
#pragma unroll
        for (int j = 0; j < 16; ++j)
            g[j] = fmaf(x, sWih[nl][j], fmaf(hp, sWhh[nl][j], sBias[nl][j]));

        float cp[4];
        *(float4*)cp = *(const float4*)&cprev[((size_t)n * B + b) * 4];

        float cn[4];
        float hsum = 0.f;
#pragma unroll
        for (int c = 0; c < 4; ++c) {
            float ig = fsig(g[c]);
            float fg = fsig(g[4 + c]);
            float gg = ftanh(g[8 + c]);
            float og = fsig(g[12 + c]);
            float cnc = fmaf(fg, cp[c], ig * gg);
            cn[c] = cnc;
            hsum = fmaf(og * ftanh(cnc), sWhr[nl][c], hsum);
        }
        *(float4*)&cnew[((size_t)n * B + b) * 4] =
            make_float4(cn[0], cn[1], cn[2], cn[3]);
        sHn[bl][nl] = hsum;
    }
    __syncthreads();

#pragma unroll
    for (int q = 0; q < 4; ++q) {
        int idx = t + 256 * q;
        int bl = idx >> 5, nl = idx & 31;
        hnew[(size_t)(b0 + bl) * N + n0 + nl] = sHn[bl][nl];
    }
}

// ---------------------------------------------------------------------------
// Launch
// ---------------------------------------------------------------------------
extern "C" void kernel_launch(void* const* d_in, const int* in_sizes, int n_in,
                              void* d_out, int out_size)
{
    const float* i_in    = (const float*)d_in[0];
    const float* h_in    = (const float*)d_in[1];
    const float* o_in    = (const float*)d_in[2];
    const float* h_cells = (const float*)d_in[3];
    const float* o_cells = (const float*)d_in[4];
    const float* W_i2h   = (const float*)d_in[5];
    const float* b_i2h   = (const float*)d_in[6];
    const float* W_h2h   = (const float*)d_in[7];
    const float* b_h2h   = (const float*)d_in[8];
    const float* W_i2o   = (const float*)d_in[9];
    const float* b_i2o   = (const float*)d_in[10];
    const float* W_h2o   = (const float*)d_in[11];
    const float* b_h2o   = (const float*)d_in[12];
    const float* Wih_h   = (const float*)d_in[13];
    const float* Whh_h   = (const float*)d_in[14];
    const float* bias_h  = (const float*)d_in[15];
    const float* Whr_h   = (const float*)d_in[16];
    const float* Wih_o   = (const float*)d_in[17];
    const float* Whh_o   = (const float*)d_in[18];
    const float* bias_o  = (const float*)d_in[19];
    const float* Whr_o   = (const float*)d_in[20];

    float* out    = (float*)d_out;
    float* new_h  = out;
    float* new_o  = new_h + (size_t)BB * NH;
    float* new_hc = new_o + (size_t)BB * NO;
    float* new_oc = new_hc + (size_t)NH * BB * CC;

    float* inh = nullptr; float* ino = nullptr;
    cudaGetSymbolAddress((void**)&inh, g_inh);
    cudaGetSymbolAddress((void**)&ino, g_ino);

    __half *if16, *hf16, *w1hh, *w2hh, *w1oh, *w2oh;
    cudaGetSymbolAddress((void**)&if16, g_i_f16);
    cudaGetSymbolAddress((void**)&hf16, g_h_f16);
    cudaGetSymbolAddress((void**)&w1hh, g_w1h_f16);
    cudaGetSymbolAddress((void**)&w2hh, g_w2h_f16);
    cudaGetSymbolAddress((void**)&w1oh, g_w1o_f16);
    cudaGetSymbolAddress((void**)&w2oh, g_w2o_f16);

    // Fused fp16 convert: one launch covering all 6 tensors, 4 float4/thread
    cvt_all<<<(unsigned)(S5 / 1024), 256>>>(
        (const float4*)i_in, (const float4*)h_in, (const float4*)W_i2h,
        (const float4*)W_h2h, (const float4*)W_i2o, (const float4*)W_h2o,
        (uint2*)if16, (uint2*)hf16,
        (uint2*)w1hh, (uint2*)w2hh, (uint2*)w1oh, (uint2*)w2oh);

    // Combined split-K2 GEMM: 1280 CTAs (2 K-halves x 640 128x64 tiles)
    constexpr int SMEM = 4 * (128 + 64) * 144;   // 4 stages x 27648B = 110592
    cudaFuncSetAttribute(gemm_f16, cudaFuncAttributeMaxDynamicSharedMemorySize, SMEM);
    gemm_f16<<<1280, 512, SMEM>>>(
        if16, hf16, w1hh, w2hh, w1oh, w2oh, inh, ino);

    // Fused pointwise for both nets (split-K reduce + agg-bias + ReLU + LSTM)
    lstm_pointwise2<<<dim3((NH + NO) / 32, BB / 32), 256>>>(
        inh, b_i2h, b_h2h, h_in, h_cells, Wih_h, Whh_h, bias_h, Whr_h,
        new_h, new_hc,
        ino, b_i2o, b_h2o, o_in, o_cells, Wih_o, Whh_o, bias_o, Whr_o,
        new_o, new_oc);
}

// round 16
// speedup vs baseline: 1.0622x; 1.0622x over previous
#include <cuda_runtime.h>
#include <cuda_fp16.h>
#include <cstdint>

// Problem constants
static constexpr int BB = 1024;   // batch
static constexpr int NI = 2048;
static constexpr int NH = 4096;
static constexpr int NO = 1024;
static constexpr int CC = 4;      // LSTM cell size
static constexpr int KTOT = NI + NH;     // 6144
static constexpr int KHALF = KTOT / 2;   // 3072

// ---------------------------------------------------------------------------
// Device scratch (no cudaMalloc allowed)
// ---------------------------------------------------------------------------
__device__ float g_inh[2 * (size_t)BB * NH];   // split-K partials
__device__ float g_ino[2 * (size_t)BB * NO];

__device__ __align__(16) __half g_i_f16[(size_t)BB * NI];
__device__ __align__(16) __half g_h_f16[(size_t)BB * NH];
__device__ __align__(16) __half g_w1h_f16[(size_t)NH * NI];
__device__ __align__(16) __half g_w2h_f16[(size_t)NH * NH];
__device__ __align__(16) __half g_w1o_f16[(size_t)NO * NI];
__device__ __align__(16) __half g_w2o_f16[(size_t)NO * NH];

// ---------------------------------------------------------------------------
// PTX helpers (portable ISA only: cp.async, ldmatrix, mma.sync)
// ---------------------------------------------------------------------------
__device__ __forceinline__ uint32_t smem_u32(const void* p) {
    uint32_t a;
    asm("{ .reg .u64 t; cvta.to.shared.u64 t, %1; cvt.u32.u64 %0, t; }"
        : "=r"(a) : "l"(p));
    return a;
}

__device__ __forceinline__ void cp16(uint32_t dst, const void* src) {
    asm volatile("cp.async.cg.shared.global [%0], [%1], 16;\n"
                 :: "r"(dst), "l"(src));
}
__device__ __forceinline__ void cp_commit() {
    asm volatile("cp.async.commit_group;\n" ::: "memory");
}
template <int N> __device__ __forceinline__ void cp_wait() {
    asm volatile("cp.async.wait_group %0;\n" :: "n"(N) : "memory");
}

__device__ __forceinline__ void ldmx4(uint32_t* r, uint32_t addr) {
    asm volatile("ldmatrix.sync.aligned.m8n8.x4.shared.b16 {%0,%1,%2,%3}, [%4];"
                 : "=r"(r[0]), "=r"(r[1]), "=r"(r[2]), "=r"(r[3]) : "r"(addr));
}

__device__ __forceinline__ void mma16816(float* c, const uint32_t* a, const uint32_t* b) {
    asm volatile(
        "mma.sync.aligned.m16n8k16.row.col.f32.f16.f16.f32 "
        "{%0,%1,%2,%3}, {%4,%5,%6,%7}, {%8,%9}, {%0,%1,%2,%3};"
        : "+f"(c[0]), "+f"(c[1]), "+f"(c[2]), "+f"(c[3])
        : "r"(a[0]), "r"(a[1]), "r"(a[2]), "r"(a[3]), "r"(b[0]), "r"(b[1]));
}

__device__ __forceinline__ uint32_t pack2h(float lo, float hi) {
    __half2 h = __floats2half2_rn(lo, hi);
    return *(uint32_t*)&h;
}

// Fast transcendentals (hardware MUFU-based, err ~1e-6 — far under budget)
__device__ __forceinline__ float fsig(float x) {
    return __fdividef(1.f, 1.f + __expf(-x));
}
__device__ __forceinline__ float ftanh(float x) {
    return fmaf(2.f, fsig(2.f * x), -1.f);
}

// ---------------------------------------------------------------------------
// Fused fp32 -> fp16 convert over all 6 tensors (1 launch, 4 float4/thread)
// ---------------------------------------------------------------------------
static constexpr size_t S0 = (size_t)BB * NI / 4;            // i
static constexpr size_t S1 = S0 + (size_t)BB * NH / 4;       // h
static constexpr size_t S2 = S1 + (size_t)NH * NI / 4;       // W_i2h
static constexpr size_t S3 = S2 + (size_t)NH * NH / 4;       // W_h2h
static constexpr size_t S4 = S3 + (size_t)NO * NI / 4;       // W_i2o
static constexpr size_t S5 = S4 + (size_t)NO * NH / 4;       // W_h2o

__global__ __launch_bounds__(256) void cvt_all(
    const float4* __restrict__ p0, const float4* __restrict__ p1,
    const float4* __restrict__ p2, const float4* __restrict__ p3,
    const float4* __restrict__ p4, const float4* __restrict__ p5,
    uint2* __restrict__ h0, uint2* __restrict__ h1,
    uint2* __restrict__ h2, uint2* __restrict__ h3,
    uint2* __restrict__ h4, uint2* __restrict__ h5)
{
#pragma unroll
    for (int rep = 0; rep < 4; ++rep) {
        size_t i = (size_t)blockIdx.x * 1024 + rep * 256 + threadIdx.x;
        const float4* src; uint2* hi; size_t base;
        if      (i < S0) { src = p0; hi = h0; base = 0;  }
        else if (i < S1) { src = p1; hi = h1; base = S0; }
        else if (i < S2) { src = p2; hi = h2; base = S1; }
        else if (i < S3) { src = p3; hi = h3; base = S2; }
        else if (i < S4) { src = p4; hi = h4; base = S3; }
        else             { src = p5; hi = h5; base = S4; }
        size_t j = i - base;
        float4 v = src[j];
        uint2 H;
        H.x = pack2h(v.x, v.y);
        H.y = pack2h(v.z, v.w);
        hi[j] = H;
    }
}

// ---------------------------------------------------------------------------
// Combined split-K2 mma.sync GEMM (pure fp16), CTA tile 128x64, one launch.
//   blockIdx.x in [0, 1280): kh = bid & 1 (K half), tb = bid >> 1 (tile id)
//     tb [0,512):   inh tile: m0=(tb>>6)*128, n0=(tb&63)*64   (N=4096)
//     tb [512,640): ino tile: m0=(r>>4)*128,  n0=(r&15)*64    (N=1024)
// NO bias/ReLU here: partials reduced (+bias+ReLU) in lstm_pointwise.
// 512 threads = 16 warps (8m x 2n), warp tile 16x32, BK=64.
// 4-stage cp.async pipeline, ONE barrier per chunk, loads issued AFTER the
// MMA block (warp-staggered issue). Safety: the write at iter c targets stage
// (c+3)%4 = (c-1)%4; every warp's ldmatrix reads of that stage (chunk c-1)
// completed, in its own program order, before it arrived at iter-c's barrier.
// ---------------------------------------------------------------------------
__global__ __launch_bounds__(512, 1) void gemm_f16(
    const __half* __restrict__ iF, const __half* __restrict__ hF,
    const __half* __restrict__ w1h, const __half* __restrict__ w2h,
    const __half* __restrict__ w1o, const __half* __restrict__ w2o,
    float* __restrict__ outh, float* __restrict__ outo)
{
    constexpr int ROWB  = 144;             // 64 fp16 = 128B + 16B pad
    constexpr int ATILE = 128 * ROWB;      // 18432 B
    constexpr int WTILE = 64 * ROWB;       //  9216 B
    constexpr int STAGE = ATILE + WTILE;   // 27648 B

    extern __shared__ char smraw[];
    const uint32_t sb = smem_u32(smraw);

    const int t = threadIdx.x, wid = t >> 5, lane = t & 31;
    const int wm = wid >> 1, wn = wid & 1;   // 8m x 2n, warp tile 16x32

    const int bid = blockIdx.x;
    const int kh = bid & 1;
    const int tb = bid >> 1;
    const int kbase = kh * KHALF;

    const __half *W1, *W2;
    float* out;
    int m0, n0, N;
    if (tb < 512) {
        m0 = (tb >> 6) * 128; n0 = (tb & 63) * 64; N = NH;
        W1 = w1h; W2 = w2h;
        out = outh + (size_t)kh * BB * NH;
    } else {
        int r = tb - 512;
        m0 = (r >> 4) * 128; n0 = (r & 15) * 64; N = NO;
        W1 = w1o; W2 = w2o;
        out = outo + (size_t)kh * BB * NO;
    }

    // ldmatrix per-lane byte offsets within a tile
    const uint32_t aOff = (uint32_t)((wm * 16 + (lane & 15)) * ROWB + (lane >> 4) * 16);
    const uint32_t bOff = (uint32_t)((wn * 32 + ((lane >> 4) << 3) + (lane & 7)) * ROWB
                                     + ((lane >> 3) & 1) * 16);

    float acc[4][4];
#pragma unroll
    for (int j = 0; j < 4; ++j)
#pragma unroll
        for (int k = 0; k < 4; ++k) acc[j][k] = 0.f;

    constexpr int NC = KHALF / 64;   // 48 chunks

    auto load_chunk = [&](int c, int s) {
        const int k0 = kbase + c * 64;
        const __half *Ap, *Wp;
        int lda, ko;
        if (k0 < NI) { Ap = iF; Wp = W1; lda = NI; ko = k0; }
        else         { Ap = hF; Wp = W2; lda = NH; ko = k0 - NI; }
        const uint32_t st = sb + (uint32_t)s * STAGE;
        // A: 128 rows x 8 x 16B = 1024 transfers (2 per thread)
#pragma unroll
        for (int q = 0; q < 2; ++q) {
            int idx = q * 512 + t;
            int row = idx >> 3, ch = idx & 7;
            cp16(st + (uint32_t)(row * ROWB + ch * 16),
                 Ap + (size_t)(m0 + row) * lda + ko + ch * 8);
        }
        // W: 64 rows x 8 x 16B = 512 transfers (1 per thread)
        {
            int row = t >> 3, ch = t & 7;
            cp16(st + ATILE + (uint32_t)(row * ROWB + ch * 16),
                 Wp + (size_t)(n0 + row) * lda + ko + ch * 8);
        }
    };

    // Prologue: fill 3 of the 4 stages
    load_chunk(0, 0); cp_commit();
    load_chunk(1, 1); cp_commit();
    load_chunk(2, 2); cp_commit();

    for (int c = 0; c < NC; ++c) {
        cp_wait<2>();                // chunk c's groups retired
        __syncthreads();             // all warps see stage c%4; also proves all
                                     // warps finished reading stage (c+3)%4

        const uint32_t ast = sb + (uint32_t)(c & 3) * STAGE;
        const uint32_t wst = ast + ATILE;
#pragma unroll
        for (int kk = 0; kk < 4; ++kk) {
            uint32_t ah[4];
            ldmx4(ah, ast + aOff + (uint32_t)(kk * 32));
            uint32_t bh[2][4];
#pragma unroll
            for (int p = 0; p < 2; ++p)
                ldmx4(bh[p], wst + bOff + (uint32_t)(p * 16 * ROWB + kk * 32));
#pragma unroll
            for (int nt = 0; nt < 4; ++nt)
                mma16816(acc[nt], ah, &bh[nt >> 1][(nt & 1) * 2]);
        }

        if (c + 3 < NC) load_chunk(c + 3, (c + 3) & 3);
        cp_commit();                 // one group per iteration (empty at tail)
    }

    // Epilogue: raw partial store (bias/ReLU applied at reduce in pointwise)
    const int g = lane >> 2, q2 = (lane & 3) * 2;
#pragma unroll
    for (int nt = 0; nt < 4; ++nt) {
        int col = n0 + wn * 32 + nt * 8 + q2;
        int r0 = m0 + wm * 16 + g;
        *(float2*)&out[(size_t)r0 * N + col] = make_float2(acc[nt][0], acc[nt][1]);
        *(float2*)&out[(size_t)(r0 + 8) * N + col] = make_float2(acc[nt][2], acc[nt][3]);
    }
}

// ---------------------------------------------------------------------------
// Fused per-node LSTM pointwise for BOTH nets in one launch, with
// split-K reduce + agg bias + ReLU:  x = relu(xp0 + xp1 + ab1[n] + ab2[n])
//   blockIdx.x [0,128): h-net (N=4096), [128,160): o-net (N=1024)
// ---------------------------------------------------------------------------
__global__ __launch_bounds__(256) void lstm_pointwise2(
    const float* __restrict__ xph, const float* __restrict__ b_i2h,
    const float* __restrict__ b_h2h,
    const float* __restrict__ h_in, const float* __restrict__ h_cells,
    const float* __restrict__ Wih_h, const float* __restrict__ Whh_h,
    const float* __restrict__ bias_h, const float* __restrict__ Whr_h,
    float* __restrict__ new_h, float* __restrict__ new_hc,
    const float* __restrict__ xpo, const float* __restrict__ b_i2o,
    const float* __restrict__ b_h2o,
    const float* __restrict__ o_in, const float* __restrict__ o_cells,
    const float* __restrict__ Wih_o, const float* __restrict__ Whh_o,
    const float* __restrict__ bias_o, const float* __restrict__ Whr_o,
    float* __restrict__ new_o, float* __restrict__ new_oc)
{
    __shared__ float sX[32][33];
    __shared__ float sH[32][33];
    __shared__ float sHn[32][33];
    __shared__ float sWih[32][16];
    __shared__ float sWhh[32][16];
    __shared__ float sBias[32][16];
    __shared__ float sWhr[32][4];
    __shared__ float sAggB[32];

    const int t = threadIdx.x;
    const int bx = blockIdx.x;
    const int b0 = blockIdx.y * 32;

    const float *xp0, *ab1, *ab2, *hprev, *cprev, *Wih, *Whh, *bias, *Whr;
    float *hnew, *cnew;
    int N, n0;
    if (bx < NH / 32) {
        N = NH; n0 = bx * 32;
        xp0 = xph; ab1 = b_i2h; ab2 = b_h2h; hprev = h_in; cprev = h_cells;
        Wih = Wih_h; Whh = Whh_h; bias = bias_h; Whr = Whr_h;
        hnew = new_h; cnew = new_hc;
    } else {
        N = NO; n0 = (bx - NH / 32) * 32;
        xp0 = xpo; ab1 = b_i2o; ab2 = b_h2o; hprev = o_in; cprev = o_cells;
        Wih = Wih_o; Whh = Whh_o; bias = bias_o; Whr = Whr_o;
        hnew = new_o; cnew = new_oc;
    }
    const float* xp1 = xp0 + (size_t)BB * N;   // second split-K partial
    const int B = BB;

    if (t < 128) {
        int nl = t >> 2, w = t & 3;
        ((float4*)&sWih[nl][0])[w]  = ((const float4*)Wih)[(size_t)(n0 + nl) * 4 + w];
        ((float4*)&sWhh[nl][0])[w]  = ((const float4*)Whh)[(size_t)(n0 + nl) * 4 + w];
        ((float4*)&sBias[nl][0])[w] = ((const float4*)bias)[(size_t)(n0 + nl) * 4 + w];
    }
    if (t < 32) {
        *(float4*)&sWhr[t][0] = ((const float4*)Whr)[(size_t)(n0 + t)];
        sAggB[t] = ab1[n0 + t] + ab2[n0 + t];
    }

#pragma unroll
    for (int q = 0; q < 4; ++q) {
        int idx = t + 256 * q;
        int bl = idx >> 5, nl = idx & 31;
        size_t gi = (size_t)(b0 + bl) * N + n0 + nl;
        sX[bl][nl] = xp0[gi] + xp1[gi];
        sH[bl][nl] = hprev[gi];
    }
    __syncthreads();

#pragma unroll
    for (int q = 0; q < 4; ++q) {
        int idx = t + 256 * q;
        int bl = idx & 31, nl = idx >> 5;
        int n = n0 + nl, b = b0 + bl;

        float x  = fmaxf(sX[bl][nl] + sAggB[nl], 0.f);   // reduce + bias + ReLU
        float hp = sH[bl][nl];

        float g[16];
#pragma unroll
        for (int j = 0; j < 16; ++j)
            g[j] = fmaf(x, sWih[nl][j], fmaf(hp, sWhh[nl][j], sBias[nl][j]));

        float cp[4];
        *(float4*)cp = *(const float4*)&cprev[((size_t)n * B + b) * 4];

        float cn[4];
        float hsum = 0.f;
#pragma unroll
        for (int c = 0; c < 4; ++c) {
            float ig = fsig(g[c]);
            float fg = fsig(g[4 + c]);
            float gg = ftanh(g[8 + c]);
            float og = fsig(g[12 + c]);
            float cnc = fmaf(fg, cp[c], ig * gg);
            cn[c] = cnc;
            hsum = fmaf(og * ftanh(cnc), sWhr[nl][c], hsum);
        }
        *(float4*)&cnew[((size_t)n * B + b) * 4] =
            make_float4(cn[0], cn[1], cn[2], cn[3]);
        sHn[bl][nl] = hsum;
    }
    __syncthreads();

#pragma unroll
    for (int q = 0; q < 4; ++q) {
        int idx = t + 256 * q;
        int bl = idx >> 5, nl = idx & 31;
        hnew[(size_t)(b0 + bl) * N + n0 + nl] = sHn[bl][nl];
    }
}

// ---------------------------------------------------------------------------
// Launch
// ---------------------------------------------------------------------------
extern "C" void kernel_launch(void* const* d_in, const int* in_sizes, int n_in,
                              void* d_out, int out_size)
{
    const float* i_in    = (const float*)d_in[0];
    const float* h_in    = (const float*)d_in[1];
    const float* o_in    = (const float*)d_in[2];
    const float* h_cells = (const float*)d_in[3];
    const float* o_cells = (const float*)d_in[4];
    const float* W_i2h   = (const float*)d_in[5];
    const float* b_i2h   = (const float*)d_in[6];
    const float* W_h2h   = (const float*)d_in[7];
    const float* b_h2h   = (const float*)d_in[8];
    const float* W_i2o   = (const float*)d_in[9];
    const float* b_i2o   = (const float*)d_in[10];
    const float* W_h2o   = (const float*)d_in[11];
    const float* b_h2o   = (const float*)d_in[12];
    const float* Wih_h   = (const float*)d_in[13];
    const float* Whh_h   = (const float*)d_in[14];
    const float* bias_h  = (const float*)d_in[15];
    const float* Whr_h   = (const float*)d_in[16];
    const float* Wih_o   = (const float*)d_in[17];
    const float* Whh_o   = (const float*)d_in[18];
    const float* bias_o  = (const float*)d_in[19];
    const float* Whr_o   = (const float*)d_in[20];

    float* out    = (float*)d_out;
    float* new_h  = out;
    float* new_o  = new_h + (size_t)BB * NH;
    float* new_hc = new_o + (size_t)BB * NO;
    float* new_oc = new_hc + (size_t)NH * BB * CC;

    float* inh = nullptr; float* ino = nullptr;
    cudaGetSymbolAddress((void**)&inh, g_inh);
    cudaGetSymbolAddress((void**)&ino, g_ino);

    __half *if16, *hf16, *w1hh, *w2hh, *w1oh, *w2oh;
    cudaGetSymbolAddress((void**)&if16, g_i_f16);
    cudaGetSymbolAddress((void**)&hf16, g_h_f16);
    cudaGetSymbolAddress((void**)&w1hh, g_w1h_f16);
    cudaGetSymbolAddress((void**)&w2hh, g_w2h_f16);
    cudaGetSymbolAddress((void**)&w1oh, g_w1o_f16);
    cudaGetSymbolAddress((void**)&w2oh, g_w2o_f16);

    // Fused fp16 convert: one launch covering all 6 tensors, 4 float4/thread
    cvt_all<<<(unsigned)(S5 / 1024), 256>>>(
        (const float4*)i_in, (const float4*)h_in, (const float4*)W_i2h,
        (const float4*)W_h2h, (const float4*)W_i2o, (const float4*)W_h2o,
        (uint2*)if16, (uint2*)hf16,
        (uint2*)w1hh, (uint2*)w2hh, (uint2*)w1oh, (uint2*)w2oh);

    // Combined split-K2 GEMM: 1280 CTAs (2 K-halves x 640 128x64 tiles)
    constexpr int SMEM = 4 * (128 + 64) * 144;   // 4 stages x 27648B = 110592
    cudaFuncSetAttribute(gemm_f16, cudaFuncAttributeMaxDynamicSharedMemorySize, SMEM);
    gemm_f16<<<1280, 512, SMEM>>>(
        if16, hf16, w1hh, w2hh, w1oh, w2oh, inh, ino);

    // Fused pointwise for both nets (split-K reduce + agg-bias + ReLU + LSTM)
    lstm_pointwise2<<<dim3((NH + NO) / 32, BB / 32), 256>>>(
        inh, b_i2h, b_h2h, h_in, h_cells, Wih_h, Whh_h, bias_h, Whr_h,
        new_h, new_hc,
        ino, b_i2o, b_h2o, o_in, o_cells, Wih_o, Whh_o, bias_o, Whr_o,
        new_o, new_oc);
}